// round 12
// baseline (speedup 1.0000x reference)
#include <cuda_runtime.h>

#define N_NODES   100000
#define N_EDGES   1600000
#define D_FEAT    64
#define F4_PER_ROW (D_FEAT / 4)       // 16
#define NCHAIN    8                   // chains per node; half-warp chases 4, interleaved

// -------- scratch (static __device__; no allocation) --------
__device__ int  g_head[NCHAIN * N_NODES];     // 3.2 MB; memset to 0xFF each call
__device__ int2 g_link[N_EDGES];              // (next_edge, src_node), 12.8 MB

// -------- build: one atomicExch per edge, coalesced link store --------
__global__ void k_build(const int* __restrict__ edge_index, int E) {
    int e = blockIdx.x * blockDim.x + threadIdx.x;
    if (e >= E) return;
    int s = __ldg(&edge_index[e]);            // src
    int d = __ldg(&edge_index[E + e]);        // dst
    int bucket = NCHAIN * d + (e & (NCHAIN - 1));
    int old = atomicExch(&g_head[bucket], e);
    g_link[e] = make_int2(old, s);
}

__device__ __forceinline__ float4 fmax4(float4 a, float4 b) {
    a.x = fmaxf(a.x, b.x); a.y = fmaxf(a.y, b.y);
    a.z = fmaxf(a.z, b.z); a.w = fmaxf(a.w, b.w);
    return a;
}

// One warp per node. 8 chains; half-warp hw chases chains {4hw..4hw+3}
// interleaved: 4 independent link loads + 4 independent row loads in
// flight per iteration, serial depth ~deg/8.
__global__ void k_aggregate(const float* __restrict__ h,
                            float* __restrict__ out, int n) {
    int warp = (blockIdx.x * blockDim.x + threadIdx.x) >> 5;
    int lane = threadIdx.x & 31;
    if (warp >= n) return;

    int hw = lane >> 4;
    int fl = lane & 15;

    const int4* heads4 = reinterpret_cast<const int4*>(g_head);
    int4 ha = __ldg(&heads4[2 * warp]);       // chains 0..3 (broadcast)
    int4 hb = __ldg(&heads4[2 * warp + 1]);   // chains 4..7 (broadcast)

    bool isolated = (ha.x < 0) & (ha.y < 0) & (ha.z < 0) & (ha.w < 0) &
                    (hb.x < 0) & (hb.y < 0) & (hb.z < 0) & (hb.w < 0);

    int4 mine = (hw == 0) ? ha : hb;
    int e0 = mine.x, e1 = mine.y, e2 = mine.z, e3 = mine.w;

    const float NEG_INF = __int_as_float(0xff800000);
    float4 acc = make_float4(NEG_INF, NEG_INF, NEG_INF, NEG_INF);

    const float4* __restrict__ h4 = reinterpret_cast<const float4*>(h);

    while (e0 >= 0 || e1 >= 0 || e2 >= 0 || e3 >= 0) {
        int2 l0, l1, l2, l3;
        bool a0 = (e0 >= 0), a1 = (e1 >= 0), a2 = (e2 >= 0), a3 = (e3 >= 0);
        if (a0) l0 = __ldg(&g_link[e0]);      // 4 independent link loads
        if (a1) l1 = __ldg(&g_link[e1]);
        if (a2) l2 = __ldg(&g_link[e2]);
        if (a3) l3 = __ldg(&g_link[e3]);
        float4 v0, v1, v2, v3;
        if (a0) v0 = __ldg(&h4[l0.y * F4_PER_ROW + fl]);   // 4 independent rows
        if (a1) v1 = __ldg(&h4[l1.y * F4_PER_ROW + fl]);
        if (a2) v2 = __ldg(&h4[l2.y * F4_PER_ROW + fl]);
        if (a3) v3 = __ldg(&h4[l3.y * F4_PER_ROW + fl]);
        if (a0) { acc = fmax4(acc, v0); e0 = l0.x; }
        if (a1) { acc = fmax4(acc, v1); e1 = l1.x; }
        if (a2) { acc = fmax4(acc, v2); e2 = l2.x; }
        if (a3) { acc = fmax4(acc, v3); e3 = l3.x; }
    }

    // combine the two half-warps (same feature chunk at lane and lane^16)
    acc.x = fmaxf(acc.x, __shfl_xor_sync(0xffffffffu, acc.x, 16));
    acc.y = fmaxf(acc.y, __shfl_xor_sync(0xffffffffu, acc.y, 16));
    acc.z = fmaxf(acc.z, __shfl_xor_sync(0xffffffffu, acc.z, 16));
    acc.w = fmaxf(acc.w, __shfl_xor_sync(0xffffffffu, acc.w, 16));

    if (isolated) acc = make_float4(0.f, 0.f, 0.f, 0.f);

    if (lane < 16)
        reinterpret_cast<float4*>(out)[warp * F4_PER_ROW + fl] = acc;
}

// -------- launch: memset + 2 kernels --------
extern "C" void kernel_launch(void* const* d_in, const int* in_sizes, int n_in,
                              void* d_out, int out_size) {
    const float* h = (const float*)d_in[0];
    const int* edge_index = (const int*)d_in[1];
    float* out = (float*)d_out;

    const int N = in_sizes[0] / D_FEAT;      // 100000
    const int E = in_sizes[1] / 2;           // 1600000

    void* p_head = nullptr;
    cudaGetSymbolAddress(&p_head, g_head);
    cudaMemsetAsync(p_head, 0xFF, (size_t)NCHAIN * N * sizeof(int));

    const int T = 256;
    k_build<<<(E + T - 1) / T, T>>>(edge_index, E);

    int blocks = (N * 32 + T - 1) / T;       // 12500
    k_aggregate<<<blocks, T>>>(h, out, N);
}

// round 13
// speedup vs baseline: 1.9774x; 1.9774x over previous
#include <cuda_runtime.h>

#define N_NODES   100000
#define N_EDGES   1600000
#define D_FEAT    64
#define F4_PER_ROW (D_FEAT / 4)       // 16
#define NSUB      4                   // counter split factor (collision 16 -> 4)
#define T         256

// -------- scratch (static __device__; no allocation, no memsets) --------
__device__ int4 g_cnt4[N_NODES];      // zero at load; k_alloc re-zeroes after read
__device__ int2 g_span[N_NODES];      // (start, deg)
__device__ int4 g_fill4[N_NODES];     // absolute sub-cursors for the 4 sub-buckets
__device__ int  g_csr[N_EDGES];       // dense 6.4 MB index list
__device__ int  g_cursor;             // zero at load; reset by k_aggregate

// ---- 1) count: RED.ADD into 4-way split counters ----
__global__ void k_count(const int* __restrict__ edge_index, int E) {
    int e = blockIdx.x * blockDim.x + threadIdx.x;
    if (e >= E) return;
    int d = __ldg(&edge_index[E + e]);
    atomicAdd(&reinterpret_cast<int*>(g_cnt4)[NSUB * d + (e & (NSUB - 1))], 1);
}

// ---- 2) alloc: per-node span via block scan + 1 global atomic/block ----
__global__ void k_alloc(int n) {
    __shared__ int sh[T];
    __shared__ int s_base;
    int tid = threadIdx.x;
    int i = blockIdx.x * T + tid;

    int4 c = make_int4(0, 0, 0, 0);
    if (i < n) {
        c = __ldcg(&g_cnt4[i]);
        __stcg(&g_cnt4[i], make_int4(0, 0, 0, 0));   // reset for next replay
    }
    int deg = c.x + c.y + c.z + c.w;

    sh[tid] = deg;
    __syncthreads();
    #pragma unroll
    for (int off = 1; off < T; off <<= 1) {
        int t = (tid >= off) ? sh[tid - off] : 0;
        __syncthreads();
        sh[tid] += t;
        __syncthreads();
    }
    if (tid == T - 1) s_base = atomicAdd(&g_cursor, sh[T - 1]);
    __syncthreads();

    if (i < n) {
        int start = s_base + sh[tid] - deg;          // exclusive within block
        g_span[i] = make_int2(start, deg);
        g_fill4[i] = make_int4(start,
                               start + c.x,
                               start + c.x + c.y,
                               start + c.x + c.y + c.z);
    }
}

// ---- 3) fill: one 4-way-collision atomic per edge, dense scatter ----
__global__ void k_fill(const int* __restrict__ edge_index, int E) {
    int e = blockIdx.x * blockDim.x + threadIdx.x;
    if (e >= E) return;
    int s = __ldg(&edge_index[e]);
    int d = __ldg(&edge_index[E + e]);
    int pos = atomicAdd(&reinterpret_cast<int*>(g_fill4)[NSUB * d + (e & (NSUB - 1))], 1);
    g_csr[pos] = s;
}

__device__ __forceinline__ float4 fmax4(float4 a, float4 b) {
    a.x = fmaxf(a.x, b.x); a.y = fmaxf(a.y, b.y);
    a.z = fmaxf(a.z, b.z); a.w = fmaxf(a.w, b.w);
    return a;
}

// ---- 4) aggregate: the proven dense kernel (one warp/node, 4 rows/iter) ----
// Out-of-range indices clamp to end-1 (duplicate under max = no-op).
__global__ void k_aggregate(const float* __restrict__ h,
                            float* __restrict__ out, int n) {
    int gtid = blockIdx.x * blockDim.x + threadIdx.x;
    if (gtid == 0) __stcg(&g_cursor, 0);             // reset for next replay

    int warp = gtid >> 5;
    int lane = threadIdx.x & 31;
    if (warp >= n) return;

    int2 span = __ldg(&g_span[warp]);
    int start = span.x;
    int end   = span.x + span.y;
    int hw = lane >> 4;
    int fl = lane & 15;

    const float NEG_INF = __int_as_float(0xff800000);
    float4 acc = make_float4(NEG_INF, NEG_INF, NEG_INF, NEG_INF);

    const float4* __restrict__ h4 = reinterpret_cast<const float4*>(h);

    for (int base = start; base < end; base += 8) {
        int e1 = end - 1;
        int i0 = min(base +     hw, e1);
        int i1 = min(base + 2 + hw, e1);
        int i2 = min(base + 4 + hw, e1);
        int i3 = min(base + 6 + hw, e1);
        int s0 = __ldg(&g_csr[i0]);
        int s1 = __ldg(&g_csr[i1]);
        int s2 = __ldg(&g_csr[i2]);
        int s3 = __ldg(&g_csr[i3]);
        float4 v0 = __ldg(&h4[s0 * F4_PER_ROW + fl]);
        float4 v1 = __ldg(&h4[s1 * F4_PER_ROW + fl]);
        float4 v2 = __ldg(&h4[s2 * F4_PER_ROW + fl]);
        float4 v3 = __ldg(&h4[s3 * F4_PER_ROW + fl]);
        acc = fmax4(acc, fmax4(fmax4(v0, v1), fmax4(v2, v3)));
    }

    acc.x = fmaxf(acc.x, __shfl_xor_sync(0xffffffffu, acc.x, 16));
    acc.y = fmaxf(acc.y, __shfl_xor_sync(0xffffffffu, acc.y, 16));
    acc.z = fmaxf(acc.z, __shfl_xor_sync(0xffffffffu, acc.z, 16));
    acc.w = fmaxf(acc.w, __shfl_xor_sync(0xffffffffu, acc.w, 16));

    if (span.y == 0) acc = make_float4(0.f, 0.f, 0.f, 0.f);

    if (lane < 16)
        reinterpret_cast<float4*>(out)[warp * F4_PER_ROW + fl] = acc;
}

// -------- launch: four graph nodes --------
extern "C" void kernel_launch(void* const* d_in, const int* in_sizes, int n_in,
                              void* d_out, int out_size) {
    const float* h = (const float*)d_in[0];
    const int* edge_index = (const int*)d_in[1];
    float* out = (float*)d_out;

    const int N = in_sizes[0] / D_FEAT;      // 100000
    const int E = in_sizes[1] / 2;           // 1600000

    k_count<<<(E + T - 1) / T, T>>>(edge_index, E);
    k_alloc<<<(N + T - 1) / T, T>>>(N);
    k_fill<<<(E + T - 1) / T, T>>>(edge_index, E);

    int blocks = (N * 32 + T - 1) / T;       // 12500
    k_aggregate<<<blocks, T>>>(h, out, N);
}

// round 14
// speedup vs baseline: 2.0315x; 1.0274x over previous
#include <cuda_runtime.h>
#include <cuda_fp16.h>

#define N_NODES   100000
#define N_EDGES   1600000
#define D_FEAT    64
#define I4_PER_ROW 8                  // 64 halves = 8 int4 per fp16 row
#define NSUB      4
#define T         256

// -------- scratch (static __device__; no allocation, no memsets) --------
__device__ int4 g_h16[N_NODES * I4_PER_ROW];  // fp16 mailbox, 12.8 MB
__device__ int4 g_cnt4[N_NODES];      // zero at load; k_alloc re-zeroes after read
__device__ int  g_pos[N_EDGES];       // per-edge rank within (dst, sub) bucket
__device__ int2 g_span[N_NODES];      // (start, deg)
__device__ int4 g_base4[N_NODES];     // absolute sub-bucket starts (read-only in fill)
__device__ int  g_csr[N_EDGES];       // dense 6.4 MB index list
__device__ int  g_cursor;             // zero at load; reset by k_aggregate

static __device__ __forceinline__ unsigned pack_h2(float x, float y) {
    __half2 p = __floats2half2_rn(x, y);
    return *reinterpret_cast<unsigned*>(&p);
}
static __device__ __forceinline__ unsigned hmax2u(unsigned a, unsigned b) {
    __half2 ha = *reinterpret_cast<__half2*>(&a);
    __half2 hb = *reinterpret_cast<__half2*>(&b);
    __half2 r = __hmax2(ha, hb);
    return *reinterpret_cast<unsigned*>(&r);
}
static __device__ __forceinline__ int4 hmax4x2(int4 a, int4 b) {
    a.x = (int)hmax2u((unsigned)a.x, (unsigned)b.x);
    a.y = (int)hmax2u((unsigned)a.y, (unsigned)b.y);
    a.z = (int)hmax2u((unsigned)a.z, (unsigned)b.z);
    a.w = (int)hmax2u((unsigned)a.w, (unsigned)b.w);
    return a;
}

// ---- 1) prep: count (with rank capture) + fp32->fp16 convert, fused ----
__global__ void k_prep(const float* __restrict__ h,
                       const int* __restrict__ edge_index, int E, int M) {
    int t = blockIdx.x * blockDim.x + threadIdx.x;
    if (t < E) {
        int d = __ldg(&edge_index[E + t]);
        int p = atomicAdd(&reinterpret_cast<int*>(g_cnt4)[NSUB * d + (t & (NSUB - 1))], 1);
        g_pos[t] = p;
    } else {
        int j = t - E;
        if (j < M) {   // M = N_NODES * I4_PER_ROW; each j converts 8 floats -> int4
            const float4* h4 = reinterpret_cast<const float4*>(h);
            float4 a = __ldg(&h4[2 * j]);
            float4 b = __ldg(&h4[2 * j + 1]);
            int4 r;
            r.x = (int)pack_h2(a.x, a.y);
            r.y = (int)pack_h2(a.z, a.w);
            r.z = (int)pack_h2(b.x, b.y);
            r.w = (int)pack_h2(b.z, b.w);
            g_h16[j] = r;
        }
    }
}

// ---- 2) alloc: per-node span via block scan + 1 global atomic/block ----
__global__ void k_alloc(int n) {
    __shared__ int sh[T];
    __shared__ int s_base;
    int tid = threadIdx.x;
    int i = blockIdx.x * T + tid;

    int4 c = make_int4(0, 0, 0, 0);
    if (i < n) {
        c = __ldcg(&g_cnt4[i]);
        __stcg(&g_cnt4[i], make_int4(0, 0, 0, 0));   // reset for next replay
    }
    int deg = c.x + c.y + c.z + c.w;

    sh[tid] = deg;
    __syncthreads();
    #pragma unroll
    for (int off = 1; off < T; off <<= 1) {
        int t = (tid >= off) ? sh[tid - off] : 0;
        __syncthreads();
        sh[tid] += t;
        __syncthreads();
    }
    if (tid == T - 1) s_base = atomicAdd(&g_cursor, sh[T - 1]);
    __syncthreads();

    if (i < n) {
        int start = s_base + sh[tid] - deg;
        g_span[i] = make_int2(start, deg);
        g_base4[i] = make_int4(start,
                               start + c.x,
                               start + c.x + c.y,
                               start + c.x + c.y + c.z);
    }
}

// ---- 3) fill: atomic-free scatter using captured ranks ----
__global__ void k_fill(const int* __restrict__ edge_index, int E) {
    int e = blockIdx.x * blockDim.x + threadIdx.x;
    if (e >= E) return;
    int s = __ldg(&edge_index[e]);
    int d = __ldg(&edge_index[E + e]);
    int p = __ldg(&g_pos[e]);
    int base = __ldg(&reinterpret_cast<const int*>(g_base4)[NSUB * d + (e & (NSUB - 1))]);
    g_csr[base + p] = s;
}

// ---- 4) aggregate: one warp/node, quarter-warp per fp16 row ----
// Per iteration: 8 rows via 2 idx LDG.32 + 2 row LDG.128 + 8 HMNMX2.
// Out-of-range indices clamp to end-1 (duplicate under max = no-op).
__global__ void k_aggregate(float* __restrict__ out, int n) {
    int gtid = blockIdx.x * blockDim.x + threadIdx.x;
    if (gtid == 0) __stcg(&g_cursor, 0);             // reset for next replay

    int warp = gtid >> 5;
    int lane = threadIdx.x & 31;
    if (warp >= n) return;

    int2 span = __ldg(&g_span[warp]);
    int start = span.x;
    int end   = span.x + span.y;
    int qw = lane >> 3;        // 0..3: which row of the group
    int el = lane & 7;         // int4 chunk within the 128B row

    const unsigned NEG2 = 0xFC00FC00u;               // (-inf, -inf) half2
    int4 acc = make_int4((int)NEG2, (int)NEG2, (int)NEG2, (int)NEG2);

    for (int base = start; base < end; base += 8) {
        int e1 = end - 1;
        int i0 = min(base + qw,     e1);
        int i1 = min(base + 4 + qw, e1);
        int s0 = __ldg(&g_csr[i0]);
        int s1 = __ldg(&g_csr[i1]);
        int4 v0 = __ldg(&g_h16[s0 * I4_PER_ROW + el]);
        int4 v1 = __ldg(&g_h16[s1 * I4_PER_ROW + el]);
        acc = hmax4x2(acc, v0);
        acc = hmax4x2(acc, v1);
    }

    // reduce across the 4 quarter-warps (same el at lane^8 and lane^16)
    #pragma unroll
    for (int mask = 8; mask <= 16; mask <<= 1) {
        int4 o;
        o.x = __shfl_xor_sync(0xffffffffu, acc.x, mask);
        o.y = __shfl_xor_sync(0xffffffffu, acc.y, mask);
        o.z = __shfl_xor_sync(0xffffffffu, acc.z, mask);
        o.w = __shfl_xor_sync(0xffffffffu, acc.w, mask);
        acc = hmax4x2(acc, o);
    }

    if (lane < 8) {
        float4 r0, r1;
        if (span.y == 0) {
            r0 = make_float4(0.f, 0.f, 0.f, 0.f);
            r1 = r0;
        } else {
            float2 f0 = __half22float2(*reinterpret_cast<__half2*>(&acc.x));
            float2 f1 = __half22float2(*reinterpret_cast<__half2*>(&acc.y));
            float2 f2 = __half22float2(*reinterpret_cast<__half2*>(&acc.z));
            float2 f3 = __half22float2(*reinterpret_cast<__half2*>(&acc.w));
            r0 = make_float4(f0.x, f0.y, f1.x, f1.y);
            r1 = make_float4(f2.x, f2.y, f3.x, f3.y);
        }
        float4* out4 = reinterpret_cast<float4*>(out);
        out4[warp * 16 + 2 * el]     = r0;
        out4[warp * 16 + 2 * el + 1] = r1;
    }
}

// -------- launch: four graph nodes --------
extern "C" void kernel_launch(void* const* d_in, const int* in_sizes, int n_in,
                              void* d_out, int out_size) {
    const float* h = (const float*)d_in[0];
    const int* edge_index = (const int*)d_in[1];
    float* out = (float*)d_out;

    const int N = in_sizes[0] / D_FEAT;      // 100000
    const int E = in_sizes[1] / 2;           // 1600000
    const int M = N * I4_PER_ROW;            // 800000 convert items

    int prep_items = E + M;
    k_prep<<<(prep_items + T - 1) / T, T>>>(h, edge_index, E, M);
    k_alloc<<<(N + T - 1) / T, T>>>(N);
    k_fill<<<(E + T - 1) / T, T>>>(edge_index, E);

    int blocks = (N * 32 + T - 1) / T;       // 12500
    k_aggregate<<<blocks, T>>>(out, N);
}